// round 14
// baseline (speedup 1.0000x reference)
#include <cuda_runtime.h>
#include <cuda_fp16.h>
#include <cuda_bf16.h>
#include <math.h>

#define BB 4
#define CC 64
#define OO 64
#define HH 128
#define WW 128
#define CHS (HH * WW)
#define NC4 (CC / 4)

#define WPAD 68                    // main weight row floats (272B)

// SMEM float offsets
#define WSH_F 0
#define UNI_F (576 * WPAD)         // 39168: union {wosh 18432 | exsh 7280 | vsh 18432}
#define BN_F  (UNI_F + 18432)      // 57600
#define SMEM_FLOATS (BN_F + 128)   // 57728 floats = 230,912 B

typedef unsigned long long ull;

// shingled channel-packed fp16 image:
// g_x8[b][c4][pix] = { 4 halves (ch 4c4..4c4+3) at pix, same at pix+1 (0 at row end) }
__device__ ulonglong2 g_x8[(size_t)BB * NC4 * CHS];

__device__ __forceinline__ ull pack2(float lo, float hi) {
    ull r; asm("mov.b64 %0, {%1, %2};" : "=l"(r) : "f"(lo), "f"(hi)); return r;
}
__device__ __forceinline__ void unpack2(ull v, float& lo, float& hi) {
    asm("mov.b64 {%0, %1}, %2;" : "=f"(lo), "=f"(hi) : "l"(v));
}
__device__ __forceinline__ ull ffma2(ull a, ull b, ull c) {
    ull d; asm("fma.rn.f32x2 %0, %1, %2, %3;" : "=l"(d) : "l"(a), "l"(b), "l"(c)); return d;
}

#define BAR_SYNC(id)   asm volatile("bar.sync %0, 512;"   :: "r"(id) : "memory")
#define BAR_ARRIVE(id) asm volatile("bar.arrive %0, 512;" :: "r"(id) : "memory")
#define PBAR_SYNC()    asm volatile("bar.sync 9, 256;" ::: "memory")

// ---------------------------------------------------------------------------
// Pre-pass: pack 4 channels x 2 horizontal pixels into one ulonglong2.
// ---------------------------------------------------------------------------
__global__ void __launch_bounds__(256) pack8_kernel(const float* __restrict__ x)
{
    int i = blockIdx.x * 256 + threadIdx.x;          // 0 .. BB*NC4*CHS-1
    int pix = i & (CHS - 1);
    int c4  = (i >> 14) & (NC4 - 1);
    int b   = i >> 18;
    const float* xp = x + ((size_t)(b * CC + c4 * 4) << 14) + pix;
    __half2 lo01 = __floats2half2_rn(xp[0],       xp[CHS]);
    __half2 lo23 = __floats2half2_rn(xp[2 * CHS], xp[3 * CHS]);
    bool has = (pix & (WW - 1)) < WW - 1;
    __half2 z = __floats2half2_rn(0.0f, 0.0f);
    __half2 hi01 = z, hi23 = z;
    if (has) {
        hi01 = __floats2half2_rn(xp[1],           xp[CHS + 1]);
        hi23 = __floats2half2_rn(xp[2 * CHS + 1], xp[3 * CHS + 1]);
    }
    unsigned l0 = *reinterpret_cast<unsigned*>(&lo01);
    unsigned l1 = *reinterpret_cast<unsigned*>(&lo23);
    unsigned h0 = *reinterpret_cast<unsigned*>(&hi01);
    unsigned h1 = *reinterpret_cast<unsigned*>(&hi23);
    ulonglong2 r;
    r.x = ((ull)l1 << 32) | l0;
    r.y = ((ull)h1 << 32) | h0;
    g_x8[i] = r;
}

// ---------------------------------------------------------------------------
// Fused DCNv2 + BN + ReLU. CTA = 2 rows (256 px), 512 threads.
// Phase 1 (offset conv, fp32 x): all 16 warps. Phase 2: warps 0-7 = samplers
// (2 corner-pair LDG.128 per tap deliver 4 channels at once); warps 8-15 =
// consumers (FFMA2 GEMM tile). Ring: 2 slots x 4 channels.
// ---------------------------------------------------------------------------
__global__ void __launch_bounds__(512, 1) dcn_p8_kernel(
    const float* __restrict__ x,
    const float* __restrict__ w_off,
    const float* __restrict__ b_off,
    const float* __restrict__ weight,
    const float* __restrict__ bias,
    const float* __restrict__ gamma,
    const float* __restrict__ beta,
    const float* __restrict__ rmean,
    const float* __restrict__ rvar,
    float* __restrict__ out)
{
    extern __shared__ float sm[];
    float* wsh    = sm + WSH_F;    // [576][WPAD], interleaved o-layout
    float* wosh   = sm + UNI_F;    // [576][32]   (phase 1)
    float* exsh   = sm + UNI_F;    // [28][260]   (offset exchange)
    float* vsh    = sm + UNI_F;    // [2 slots][4 ch][9][256] (phase 2 ring)
    float* bscale = sm + BN_F;
    float* bshift = bscale + 64;

    const int tid  = threadIdx.x;
    const int lane = tid & 31;
    const int w2   = tid >> 5;

    // ---- stage main weights with interleaved row layout ----
    for (int i = tid; i < OO * 576; i += 512) {
        int o = i / 576, ck = i % 576;
        int og = o >> 3, r = o & 7, ch = r >> 2, ri = r & 3;
        wsh[ck * WPAD + ch * 32 + og * 4 + ri] = weight[i];
    }
    for (int i = tid; i < 576 * 32; i += 512) wosh[i] = 0.0f;
    if (tid < 64) {
        int o = tid;
        float sc = gamma[o] * rsqrtf(rvar[o] + 1e-5f);
        bscale[o] = sc;
        bshift[o] = (bias[o] - rmean[o]) * sc + beta[o];
    }
    __syncthreads();
    for (int i = tid; i < 27 * 576; i += 512) {
        int oc = i / 576, ck = i % 576;
        int hf = (oc >= 14), j = oc - 14 * hf;
        wosh[ck * 32 + hf * 16 + j] = w_off[i];
    }
    __syncthreads();

    const int gr0 = blockIdx.x * 2;
    const int b   = gr0 >> 7;
    const float* xb = x + (size_t)b * CC * CHS;
    const ulonglong2* x8b = g_x8 + (size_t)b * NC4 * CHS;

    // =======================================================================
    // Phase 1: offset conv (all 512 threads; lane-pair split; fp32 x)
    // =======================================================================
    {
        const int p     = w2 * 16 + (lane & 15);
        const int halfp = lane >> 4;
        const int hp    = (gr0 + (p >> 7)) & 127;
        const int wp_   = p & 127;

        const int ty0[5] = {-1, -1, -1, 0, 0}, tx0[5] = {-1, 0, 1, -1, 0};
        const int ty1[5] = {0, 0, 1, 1, 1},    tx1[5] = {0, 1, -1, 0, 1};
        int p1o[5]; bool p1v[5];
#pragma unroll
        for (int j = 0; j < 5; j++) {
            int ty = halfp ? ty1[j] : ty0[j];
            int tx = halfp ? tx1[j] : tx0[j];
            int y = hp + ty, xx = wp_ + tx;
            p1v[j] = (y >= 0) & (y < HH) & (xx >= 0) & (xx < WW);
            p1o[j] = y * WW + xx;
        }
        int kord[9];
#pragma unroll
        for (int i = 0; i < 9; i++) kord[i] = halfp ? (4 + i) % 9 : i;

        ull offa[7];
        {
            int chb = halfp * 14;
#pragma unroll
            for (int j = 0; j < 7; j++) {
                int i1 = chb + 2 * j + 1;
                float lo = b_off[chb + 2 * j];
                float hi = (i1 < 27) ? b_off[i1] : 0.0f;
                offa[j] = pack2(lo, hi);
            }
        }

        const float* wbase = wosh + halfp * 16;
        for (int c = 0; c < CC; c++) {
            const float* xc = xb + c * CHS;
            float xq[5];
#pragma unroll
            for (int j = 0; j < 5; j++)
                xq[j] = p1v[j] ? __ldg(xc + p1o[j]) : 0.0f;
            float r0 = __shfl_xor_sync(0xffffffffu, halfp ? xq[1] : xq[0], 16);
            float r1 = __shfl_xor_sync(0xffffffffu, halfp ? xq[2] : xq[1], 16);
            float r2 = __shfl_xor_sync(0xffffffffu, halfp ? xq[3] : xq[2], 16);
            float r3 = __shfl_xor_sync(0xffffffffu, halfp ? xq[4] : xq[3], 16);
            ull X[9];
            X[0] = pack2(xq[0], xq[0]); X[1] = pack2(xq[1], xq[1]);
            X[2] = pack2(xq[2], xq[2]); X[3] = pack2(xq[3], xq[3]);
            X[4] = pack2(xq[4], xq[4]);
            X[5] = pack2(r0, r0); X[6] = pack2(r1, r1);
            X[7] = pack2(r2, r2); X[8] = pack2(r3, r3);

            const float* crow = wbase + c * 288;
#pragma unroll
            for (int i = 0; i < 9; i++) {
                const float* wp2 = crow + kord[i] * 32;
                ulonglong2 q0 = ((const ulonglong2*)wp2)[0];
                ulonglong2 q1 = ((const ulonglong2*)wp2)[1];
                ulonglong2 q2 = ((const ulonglong2*)wp2)[2];
                ull        q6 = ((const ull*)wp2)[6];
                offa[0] = ffma2(q0.x, X[i], offa[0]);
                offa[1] = ffma2(q0.y, X[i], offa[1]);
                offa[2] = ffma2(q1.x, X[i], offa[2]);
                offa[3] = ffma2(q1.y, X[i], offa[3]);
                offa[4] = ffma2(q2.x, X[i], offa[4]);
                offa[5] = ffma2(q2.y, X[i], offa[5]);
                offa[6] = ffma2(q6,   X[i], offa[6]);
            }
        }

        __syncthreads();   // wosh reads done; exsh may overwrite
        {
            float l[14];
#pragma unroll
            for (int j = 0; j < 7; j++) unpack2(offa[j], l[2 * j], l[2 * j + 1]);
            int chb = halfp * 14;
#pragma unroll
            for (int j = 0; j < 14; j++)
                exsh[(chb + j) * 260 + p] = l[j];
        }
        __syncthreads();   // exsh ready
    }

    // =======================================================================
    // Role split. Ring: 2 slots x 4 channels. full ids 1,2; empty ids 3,4.
    // =======================================================================
    if (tid < 256) {
        // ----------------------- SAMPLER (producer) -----------------------
        const int spx = tid;
        const int h   = (gr0 + (spx >> 7)) & 127;
        const int w   = spx & 127;

        // per-tap: top/bottom pair offsets + 4 swap-adjusted coefficients
        int   offT[9], offB[9];
        float cT0[9], cT1[9], cB0[9], cB1[9];
#pragma unroll
        for (int k = 0; k < 9; k++) {
            float oy = exsh[(2 * k) * 260 + spx];
            float ox = exsh[(2 * k + 1) * 260 + spx];
            float m  = 1.0f / (1.0f + __expf(-exsh[(18 + k) * 260 + spx]));
            float py = (float)(h + k / 3 - 1) + oy;
            float px = (float)(w + k % 3 - 1) + ox;
            float y0f = floorf(py), x0f = floorf(px);
            float dy = py - y0f, dx = px - x0f;
            int y0 = (int)y0f, x0 = (int)x0f;
            int y1 = y0 + 1,   x1 = x0 + 1;
            bool vy0 = (y0 >= 0) & (y0 < HH), vy1 = (y1 >= 0) & (y1 < HH);
            bool vx0 = (x0 >= 0) & (x0 < WW), vx1 = (x1 >= 0) & (x1 < WW);
            int cy0 = min(max(y0, 0), HH - 1), cy1 = min(max(y1, 0), HH - 1);
            int col = min(max(x0, 0), WW - 1);
            bool swap = (x0 == -1);  // pair at col 0 holds (x[0], x[1])
            float wx0 = vx0 ? (1.0f - dx) : 0.0f;
            float wx1 = vx1 ? dx : 0.0f;
            float c_lo = swap ? wx1 : wx0;
            float c_hi = swap ? 0.0f : wx1;
            float ry0 = (vy0 ? (1.0f - dy) : 0.0f) * m;
            float ry1 = (vy1 ? dy : 0.0f) * m;
            cT0[k] = ry0 * c_lo;  cT1[k] = ry0 * c_hi;
            cB0[k] = ry1 * c_lo;  cB1[k] = ry1 * c_hi;
            offT[k] = cy0 * WW + col;
            offB[k] = cy1 * WW + col;
        }
        __syncthreads();   // (A) exsh free -> vsh

        for (int cc = 0; cc < CC; cc += 4) {
            const int slot = (cc >> 2) & 1;
            if (cc >= 8) BAR_SYNC(3 + slot);             // wait empty

            const ulonglong2* xc = x8b + (cc >> 2) * CHS;   // this c4 plane
            float v0[9], v1[9], v2[9], v3[9];
#pragma unroll
            for (int k = 0; k < 9; k++) {
                ulonglong2 T = __ldg(xc + offT[k]);
                ulonglong2 Bq = __ldg(xc + offB[k]);
                // T.x: ch0..3 at col; T.y: ch0..3 at col+1 (same for Bq)
                __half2 tl01 = *reinterpret_cast<__half2*>(&T.x);
                __half2 tl23 = *(reinterpret_cast<__half2*>(&T.x) + 1);
                __half2 th01 = *reinterpret_cast<__half2*>(&T.y);
                __half2 th23 = *(reinterpret_cast<__half2*>(&T.y) + 1);
                __half2 bl01 = *reinterpret_cast<__half2*>(&Bq.x);
                __half2 bl23 = *(reinterpret_cast<__half2*>(&Bq.x) + 1);
                __half2 bh01 = *reinterpret_cast<__half2*>(&Bq.y);
                __half2 bh23 = *(reinterpret_cast<__half2*>(&Bq.y) + 1);
                float2 ftl01 = __half22float2(tl01), ftl23 = __half22float2(tl23);
                float2 fth01 = __half22float2(th01), fth23 = __half22float2(th23);
                float2 fbl01 = __half22float2(bl01), fbl23 = __half22float2(bl23);
                float2 fbh01 = __half22float2(bh01), fbh23 = __half22float2(bh23);
                float a0 = cT0[k], a1 = cT1[k], a2 = cB0[k], a3 = cB1[k];
                v0[k] = a0 * ftl01.x + a1 * fth01.x + a2 * fbl01.x + a3 * fbh01.x;
                v1[k] = a0 * ftl01.y + a1 * fth01.y + a2 * fbl01.y + a3 * fbh01.y;
                v2[k] = a0 * ftl23.x + a1 * fth23.x + a2 * fbl23.x + a3 * fbh23.x;
                v3[k] = a0 * ftl23.y + a1 * fth23.y + a2 * fbl23.y + a3 * fbh23.y;
            }
            float* vb = vsh + slot * 9216 + spx;
#pragma unroll
            for (int k = 0; k < 9; k++) vb[k * 256] = v0[k];
#pragma unroll
            for (int k = 0; k < 9; k++) vb[2304 + k * 256] = v1[k];
#pragma unroll
            for (int k = 0; k < 9; k++) vb[4608 + k * 256] = v2[k];
#pragma unroll
            for (int k = 0; k < 9; k++) vb[6912 + k * 256] = v3[k];

            PBAR_SYNC();            // producer-only: drains all producers' STS
            BAR_ARRIVE(1 + slot);   // signal full
        }
    } else {
        // ----------------------- CONSUMER ---------------------------------
        const int ctid = tid - 256;
        const int og   = ctid & 7;     // 8 outputs: o = og*8 .. og*8+7
        const int pxg  = ctid >> 3;    // 8 px: px = pxg*8 .. pxg*8+7
        const int og4  = og * 4;

        __syncthreads();   // (A)

        ull acc[32];
#pragma unroll
        for (int j = 0; j < 32; j++) acc[j] = 0ULL;

        for (int cc = 0; cc < CC; cc += 4) {
            const int slot = (cc >> 2) & 1;
            BAR_SYNC(1 + slot);                          // wait full
#pragma unroll
            for (int ci = 0; ci < 4; ci++) {
                const float* wr = wsh + (cc + ci) * (9 * WPAD);
                const float* vr = vsh + slot * 9216 + ci * 2304 + pxg * 8;
#pragma unroll
                for (int k = 0; k < 9; k++) {
                    const float* wrk = wr + k * WPAD;
                    ulonglong2 wA = *(const ulonglong2*)(wrk + og4);
                    ulonglong2 wB = *(const ulonglong2*)(wrk + 32 + og4);
                    const float* vrk = vr + k * 256;
                    float4 a  = *(const float4*)(vrk);
                    float4 bq = *(const float4*)(vrk + 4);
                    ull vv0 = pack2(a.x, a.x),   vv1 = pack2(a.y, a.y);
                    ull vv2 = pack2(a.z, a.z),   vv3 = pack2(a.w, a.w);
                    ull vv4 = pack2(bq.x, bq.x), vv5 = pack2(bq.y, bq.y);
                    ull vv6 = pack2(bq.z, bq.z), vv7 = pack2(bq.w, bq.w);
                    acc[0]  = ffma2(wA.x, vv0, acc[0]);
                    acc[1]  = ffma2(wA.x, vv1, acc[1]);
                    acc[2]  = ffma2(wA.x, vv2, acc[2]);
                    acc[3]  = ffma2(wA.x, vv3, acc[3]);
                    acc[4]  = ffma2(wA.x, vv4, acc[4]);
                    acc[5]  = ffma2(wA.x, vv5, acc[5]);
                    acc[6]  = ffma2(wA.x, vv6, acc[6]);
                    acc[7]  = ffma2(wA.x, vv7, acc[7]);
                    acc[8]  = ffma2(wA.y, vv0, acc[8]);
                    acc[9]  = ffma2(wA.y, vv1, acc[9]);
                    acc[10] = ffma2(wA.y, vv2, acc[10]);
                    acc[11] = ffma2(wA.y, vv3, acc[11]);
                    acc[12] = ffma2(wA.y, vv4, acc[12]);
                    acc[13] = ffma2(wA.y, vv5, acc[13]);
                    acc[14] = ffma2(wA.y, vv6, acc[14]);
                    acc[15] = ffma2(wA.y, vv7, acc[15]);
                    acc[16] = ffma2(wB.x, vv0, acc[16]);
                    acc[17] = ffma2(wB.x, vv1, acc[17]);
                    acc[18] = ffma2(wB.x, vv2, acc[18]);
                    acc[19] = ffma2(wB.x, vv3, acc[19]);
                    acc[20] = ffma2(wB.x, vv4, acc[20]);
                    acc[21] = ffma2(wB.x, vv5, acc[21]);
                    acc[22] = ffma2(wB.x, vv6, acc[22]);
                    acc[23] = ffma2(wB.x, vv7, acc[23]);
                    acc[24] = ffma2(wB.y, vv0, acc[24]);
                    acc[25] = ffma2(wB.y, vv1, acc[25]);
                    acc[26] = ffma2(wB.y, vv2, acc[26]);
                    acc[27] = ffma2(wB.y, vv3, acc[27]);
                    acc[28] = ffma2(wB.y, vv4, acc[28]);
                    acc[29] = ffma2(wB.y, vv5, acc[29]);
                    acc[30] = ffma2(wB.y, vv6, acc[30]);
                    acc[31] = ffma2(wB.y, vv7, acc[31]);
                }
            }
            BAR_ARRIVE(3 + slot);                        // signal empty
        }

        // ---- BN + ReLU + store: 8 outputs x 8 px ----
        const int px0 = pxg * 8;
        const int eh  = (gr0 + (px0 >> 7)) & 127;
        const int ew  = px0 & 127;
        float* opb = out + (size_t)b * OO * CHS + eh * WW + ew;
#pragma unroll
        for (int oi2 = 0; oi2 < 4; oi2++) {
            int o0 = og * 8 + 2 * oi2;
            float s0 = bscale[o0],     f0 = bshift[o0];
            float s1 = bscale[o0 + 1], f1 = bshift[o0 + 1];
            float lo[8], hi[8];
#pragma unroll
            for (int pj = 0; pj < 8; pj++)
                unpack2(acc[oi2 * 8 + pj], lo[pj], hi[pj]);
            float4 q0 = { fmaxf(lo[0] * s0 + f0, 0.0f), fmaxf(lo[1] * s0 + f0, 0.0f),
                          fmaxf(lo[2] * s0 + f0, 0.0f), fmaxf(lo[3] * s0 + f0, 0.0f) };
            float4 q1 = { fmaxf(lo[4] * s0 + f0, 0.0f), fmaxf(lo[5] * s0 + f0, 0.0f),
                          fmaxf(lo[6] * s0 + f0, 0.0f), fmaxf(lo[7] * s0 + f0, 0.0f) };
            float4 r0 = { fmaxf(hi[0] * s1 + f1, 0.0f), fmaxf(hi[1] * s1 + f1, 0.0f),
                          fmaxf(hi[2] * s1 + f1, 0.0f), fmaxf(hi[3] * s1 + f1, 0.0f) };
            float4 r1 = { fmaxf(hi[4] * s1 + f1, 0.0f), fmaxf(hi[5] * s1 + f1, 0.0f),
                          fmaxf(hi[6] * s1 + f1, 0.0f), fmaxf(hi[7] * s1 + f1, 0.0f) };
            *(float4*)(opb + (size_t)o0 * CHS)           = q0;
            *(float4*)(opb + (size_t)o0 * CHS + 4)       = q1;
            *(float4*)(opb + (size_t)(o0 + 1) * CHS)     = r0;
            *(float4*)(opb + (size_t)(o0 + 1) * CHS + 4) = r1;
        }
    }
}

// ---------------------------------------------------------------------------

extern "C" void kernel_launch(void* const* d_in, const int* in_sizes, int n_in,
                              void* d_out, int out_size)
{
    const float* x      = (const float*)d_in[0];
    const float* w_off  = (const float*)d_in[1];
    const float* b_off  = (const float*)d_in[2];
    const float* weight = (const float*)d_in[3];
    const float* bias   = (const float*)d_in[4];
    const float* gamma  = (const float*)d_in[5];
    const float* beta   = (const float*)d_in[6];
    const float* rmean  = (const float*)d_in[7];
    const float* rvar   = (const float*)d_in[8];
    float* out = (float*)d_out;

    const int smem = SMEM_FLOATS * sizeof(float);   // 230,912 B

    cudaFuncSetAttribute(dcn_p8_kernel,
                         cudaFuncAttributeMaxDynamicSharedMemorySize, smem);

    pack8_kernel<<<(BB * NC4 * CHS) / 256, 256>>>(x);
    dcn_p8_kernel<<<BB * HH / 2, 512, smem>>>(
        x, w_off, b_off, weight, bias, gamma, beta, rmean, rvar, out);
}